// round 17
// baseline (speedup 1.0000x reference)
#include <cuda_runtime.h>
#include <math.h>

#define DD   128
#define HH   8
#define EDIM 16
#define NMAX 50000
#define EMAX 800000
#define DEGPAD 51200
#define FULLMASK 0xffffffffu

typedef unsigned long long ull;
union F2U { ull u; float2 f; };

__device__ __forceinline__ void fma2(ull &d, ull a, ull b) {
    asm("fma.rn.f32x2 %0, %1, %2, %0;" : "+l"(d) : "l"(a), "l"(b));
}

// ---------------- scratch ----------------
__device__ float g_xl[NMAX * DD];
__device__ float g_xr[NMAX * DD];
__device__ float g_Wp[64 * 512];
__device__ int   g_deg[DEGPAD];          // static zero-init; re-zeroed by k_scan
__device__ int   g_off[NMAX + 1];
__device__ int   g_woff[NMAX + 1];
__device__ int   g_perm[EMAX];
__device__ ull   g_scanstate[64];        // lookback state; zeroed by k_pre
__device__ float g_sum[DD];
__device__ float g_sumsq[DD];

// ---------------- launch 1: packW + hist + zero small state ----------------
__global__ void k_pre(const float* __restrict__ Wl, const float* __restrict__ Wr,
                      const int* __restrict__ ei, int E)
{
    int i = blockIdx.x * blockDim.x + threadIdx.x;
    if (i < 64 * 512) {
        int q  = i & 3;
        int tc = (i >> 2) & 31;
        int f  = (i >> 7) & 3;
        int kp = i >> 9;
        int m = f >> 1;
        int ci = ((f & 1) << 1) | (q >> 1);
        int ki = q & 1;
        g_Wp[i] = (m ? Wr : Wl)[(kp * 2 + ki) * DD + tc * 4 + ci];
    }
    if (i < DD) { g_sum[i] = 0.f; g_sumsq[i] = 0.f; }
    if (i < 64) g_scanstate[i] = 0ull;
    if (i < E) atomicAdd(&g_deg[ei[E + i]], 1);
}

// ---------------- launch 2: decoupled-lookback scan -> g_off/g_woff ----------
#define FLAG_AGG 1ull
#define FLAG_PRE 2ull
__global__ __launch_bounds__(256) void k_scan(int n) {
    __shared__ int wtot[8], wpre[8], sExcl;
    int b = blockIdx.x, tid = threadIdx.x;
    int lane = tid & 31, w = tid >> 5;

    int4 d = ((const int4*)g_deg)[b * 256 + tid];
    ((int4*)g_deg)[b * 256 + tid] = make_int4(0, 0, 0, 0);   // reset for next call

    int s0 = d.x, s01 = s0 + d.y, s012 = s01 + d.z;
    int tsum = s012 + d.w;
    int inc = tsum;
    #pragma unroll
    for (int o = 1; o < 32; o <<= 1) {
        int u = __shfl_up_sync(FULLMASK, inc, o);
        if (lane >= o) inc += u;
    }
    if (lane == 31) wtot[w] = inc;
    __syncthreads();
    if (w == 0 && lane < 8) {
        int v = wtot[lane];
        int s = v;
        #pragma unroll
        for (int o = 1; o < 8; o <<= 1) {
            int u = __shfl_up_sync(0xffu, s, o);
            if (lane >= o) s += u;
        }
        wpre[lane] = s - v;
    }
    __syncthreads();
    int blockTotal = wpre[7] + wtot[7];

    if (tid == 0) {
        if (b == 0) {
            atomicExch(&g_scanstate[0], (FLAG_PRE << 32) | (unsigned)blockTotal);
            sExcl = 0;
        } else {
            atomicExch(&g_scanstate[b], (FLAG_AGG << 32) | (unsigned)blockTotal);
            int excl = 0;
            int look = b - 1;
            while (true) {
                ull word = atomicAdd(&g_scanstate[look], 0ull);
                ull flag = word >> 32;
                if (flag == 0) continue;
                excl += (int)(word & 0xffffffffull);
                if (flag == FLAG_PRE) break;
                look--;
            }
            atomicExch(&g_scanstate[b],
                       (FLAG_PRE << 32) | (unsigned)(excl + blockTotal));
            sExcl = excl;
        }
    }
    __syncthreads();

    int excl = inc - tsum + wpre[w] + sExcl;
    int idx = b * 1024 + tid * 4;
    if (idx     <= n) { g_off[idx]     = excl;        g_woff[idx]     = excl; }
    if (idx + 1 <= n) { g_off[idx + 1] = excl + s0;   g_woff[idx + 1] = excl + s0; }
    if (idx + 2 <= n) { g_off[idx + 2] = excl + s01;  g_woff[idx + 2] = excl + s01; }
    if (idx + 3 <= n) { g_off[idx + 3] = excl + s012; g_woff[idx + 3] = excl + s012; }
}

// ---------------- launch 3: node transform + scatter (merged) ----------------
__global__ __launch_bounds__(256, 2) void k_nodescatter(
    const int* __restrict__ x, const float* __restrict__ emb,
    const float* __restrict__ bl, const float* __restrict__ br,
    const int* __restrict__ ei, int n, int E, int nodeBlocks)
{
    __shared__ float hs[2][32 * DD];
    if (blockIdx.x >= nodeBlocks) {
        int e = (blockIdx.x - nodeBlocks) * 256 + threadIdx.x;
        if (e < E) {
            int dst = ei[E + e];
            int pos = atomicAdd(&g_woff[dst], 1);
            g_perm[pos] = e;
        }
        return;
    }

    int tid = threadIdx.x;
    int tc = tid & 31;
    int g  = tid >> 5;
    int mat = g & 1;
    int tr  = g >> 1;
    float4 bv = ((const float4*)(mat ? br : bl))[tc];
    float* gout = mat ? g_xr : g_xl;
    const float SQ = 11.313708498984761f;
    int ntiles = (n + 31) >> 5;

    int t = blockIdx.x;
    if (t >= ntiles) return;
    int cur = 0;

    {
        int base = t * 32;
        int nrows = min(32, n - base);
        for (int i = tid; i < 32 * 32; i += 256) {
            int r = i >> 5, c4 = i & 31;
            float4 v = make_float4(0.f, 0.f, 0.f, 0.f);
            if (r < nrows) {
                const float4* src = (const float4*)(emb + (size_t)x[base + r] * DD);
                v = src[c4];
                v.x *= SQ; v.y *= SQ; v.z *= SQ; v.w *= SQ;
            }
            ((float4*)hs[cur])[i] = v;
        }
    }
    __syncthreads();

    while (t < ntiles) {
        int tn = t + nodeBlocks;
        if (tn < ntiles) {
            int base = tn * 32;
            int nrows = min(32, n - base);
            for (int i = tid; i < 32 * 32; i += 256) {
                int r = i >> 5, c4 = i & 31;
                float4 v = make_float4(0.f, 0.f, 0.f, 0.f);
                if (r < nrows) {
                    const float4* src = (const float4*)(emb + (size_t)x[base + r] * DD);
                    v = src[c4];
                    v.x *= SQ; v.y *= SQ; v.z *= SQ; v.w *= SQ;
                }
                ((float4*)hs[cur ^ 1])[i] = v;
            }
        }

        ull acc[8][4];
        #pragma unroll
        for (int r = 0; r < 8; r++)
            #pragma unroll
            for (int c = 0; c < 4; c++) acc[r][c] = 0ull;

        const float* hbase = hs[cur] + tr * 8 * DD;
        const float* wbase = g_Wp + mat * 256 + tc * 4;
        #pragma unroll 2
        for (int kp = 0; kp < 64; kp++) {
            ulonglong2 L0 = *(const ulonglong2*)(wbase + kp * 512);
            ulonglong2 L1 = *(const ulonglong2*)(wbase + kp * 512 + 128);
            ull wv[4] = { L0.x, L0.y, L1.x, L1.y };
            #pragma unroll
            for (int r = 0; r < 8; r++) {
                ull hp = *(const ull*)(hbase + r * DD + 2 * kp);
                #pragma unroll
                for (int c = 0; c < 4; c++)
                    fma2(acc[r][c], hp, wv[c]);
            }
        }

        int base = t * 32;
        #pragma unroll
        for (int r = 0; r < 8; r++) {
            int row = base + tr * 8 + r;
            if (row < n) {
                F2U t0, t1, t2, t3;
                t0.u = acc[r][0]; t1.u = acc[r][1];
                t2.u = acc[r][2]; t3.u = acc[r][3];
                float4 o = make_float4(t0.f.x + t0.f.y + bv.x, t1.f.x + t1.f.y + bv.y,
                                       t2.f.x + t2.f.y + bv.z, t3.f.x + t3.f.y + bv.w);
                *(float4*)(gout + (size_t)row * DD + tc * 4) = o;
            }
        }
        __syncthreads();
        cur ^= 1;
        t = tn;
    }
}

// ---------------- launch 4 (PROFILED): fused, 2-edge interleaved -------------
__device__ __forceinline__ void edge_compute(
    const float* eew, float4 xlv, float4 xrv, float4 a4,
    const ull (&wreg)[8][4], float4 &acc, float &ds)
{
    F2U i0, i1, i2, i3;
    i0.f = make_float2(xlv.x + xrv.x, 0.f);
    i1.f = make_float2(xlv.y + xrv.y, 0.f);
    i2.f = make_float2(xlv.z + xrv.z, 0.f);
    i3.f = make_float2(xlv.w + xrv.w, 0.f);
    ull p0 = i0.u, p1 = i1.u, p2 = i2.u, p3 = i3.u;
    #pragma unroll
    for (int dp = 0; dp < 8; dp++) {
        ull a = *(const ull*)(eew + 2 * dp);
        fma2(p0, a, wreg[dp][0]);
        fma2(p1, a, wreg[dp][1]);
        fma2(p2, a, wreg[dp][2]);
        fma2(p3, a, wreg[dp][3]);
    }
    F2U u0, u1, u2, u3;
    u0.u = p0; u1.u = p1; u2.u = p2; u3.u = p3;
    float mx = u0.f.x + u0.f.y;
    float my = u1.f.x + u1.f.y;
    float mz = u2.f.x + u2.f.y;
    float mw = u3.f.x + u3.f.y;
    mx = mx > 0.f ? mx : 0.2f * mx;
    my = my > 0.f ? my : 0.2f * my;
    mz = mz > 0.f ? mz : 0.2f * mz;
    mw = mw > 0.f ? mw : 0.2f * mw;
    float s = mx * a4.x + my * a4.y + mz * a4.z + mw * a4.w;
    s += __shfl_xor_sync(FULLMASK, s, 1);
    s += __shfl_xor_sync(FULLMASK, s, 2);
    float w = __expf(s);
    ds += w;
    acc.x = fmaf(w, xlv.x, acc.x);
    acc.y = fmaf(w, xlv.y, acc.y);
    acc.z = fmaf(w, xlv.z, acc.z);
    acc.w = fmaf(w, xlv.w, acc.w);
}

// two independent edges interleaved: both SHFL/MUFU chains in flight at once
__device__ __forceinline__ void edge_compute2(
    const float* ea, const float* eb, float4 xa, float4 xb, float4 xrv,
    float4 a4, const ull (&wreg)[8][4], float4 &acc, float &ds)
{
    F2U t;
    ull pa0, pa1, pa2, pa3, pb0, pb1, pb2, pb3;
    t.f = make_float2(xa.x + xrv.x, 0.f); pa0 = t.u;
    t.f = make_float2(xa.y + xrv.y, 0.f); pa1 = t.u;
    t.f = make_float2(xa.z + xrv.z, 0.f); pa2 = t.u;
    t.f = make_float2(xa.w + xrv.w, 0.f); pa3 = t.u;
    t.f = make_float2(xb.x + xrv.x, 0.f); pb0 = t.u;
    t.f = make_float2(xb.y + xrv.y, 0.f); pb1 = t.u;
    t.f = make_float2(xb.z + xrv.z, 0.f); pb2 = t.u;
    t.f = make_float2(xb.w + xrv.w, 0.f); pb3 = t.u;
    #pragma unroll
    for (int dp = 0; dp < 8; dp++) {
        ull a = *(const ull*)(ea + 2 * dp);
        ull b = *(const ull*)(eb + 2 * dp);
        fma2(pa0, a, wreg[dp][0]); fma2(pb0, b, wreg[dp][0]);
        fma2(pa1, a, wreg[dp][1]); fma2(pb1, b, wreg[dp][1]);
        fma2(pa2, a, wreg[dp][2]); fma2(pb2, b, wreg[dp][2]);
        fma2(pa3, a, wreg[dp][3]); fma2(pb3, b, wreg[dp][3]);
    }
    F2U u;
    u.u = pa0; float ax = u.f.x + u.f.y;
    u.u = pa1; float ay = u.f.x + u.f.y;
    u.u = pa2; float az = u.f.x + u.f.y;
    u.u = pa3; float aw = u.f.x + u.f.y;
    u.u = pb0; float bx = u.f.x + u.f.y;
    u.u = pb1; float by = u.f.x + u.f.y;
    u.u = pb2; float bz = u.f.x + u.f.y;
    u.u = pb3; float bw = u.f.x + u.f.y;
    ax = ax > 0.f ? ax : 0.2f * ax;
    bx = bx > 0.f ? bx : 0.2f * bx;
    ay = ay > 0.f ? ay : 0.2f * ay;
    by = by > 0.f ? by : 0.2f * by;
    az = az > 0.f ? az : 0.2f * az;
    bz = bz > 0.f ? bz : 0.2f * bz;
    aw = aw > 0.f ? aw : 0.2f * aw;
    bw = bw > 0.f ? bw : 0.2f * bw;
    float sa = ax * a4.x;
    float sb = bx * a4.x;
    sa = fmaf(ay, a4.y, sa);
    sb = fmaf(by, a4.y, sb);
    sa = fmaf(az, a4.z, sa);
    sb = fmaf(bz, a4.z, sb);
    sa = fmaf(aw, a4.w, sa);
    sb = fmaf(bw, a4.w, sb);
    sa += __shfl_xor_sync(FULLMASK, sa, 1);
    sb += __shfl_xor_sync(FULLMASK, sb, 1);
    sa += __shfl_xor_sync(FULLMASK, sa, 2);
    sb += __shfl_xor_sync(FULLMASK, sb, 2);
    float wa = __expf(sa);
    float wb = __expf(sb);
    ds += wa;
    ds += wb;
    acc.x = fmaf(wa, xa.x, acc.x);
    acc.y = fmaf(wa, xa.y, acc.y);
    acc.z = fmaf(wa, xa.z, acc.z);
    acc.w = fmaf(wa, xa.w, acc.w);
    acc.x = fmaf(wb, xb.x, acc.x);
    acc.y = fmaf(wb, xb.y, acc.y);
    acc.z = fmaf(wb, xb.z, acc.z);
    acc.w = fmaf(wb, xb.w, acc.w);
}

#define PAIR_STAGE(QA, QB)                                                     \
    {                                                                          \
        float4 xa = QA, xb = QB;                                               \
        if (j + 4 < m) {                                                       \
            int s4 = __shfl_sync(FULLMASK, sL, j + 4);                         \
            QA = *(const float4*)(g_xl + (size_t)s4 * DD + col);               \
        }                                                                      \
        if (j + 5 < m) {                                                       \
            int s5 = __shfl_sync(FULLMASK, sL, j + 5);                         \
            QB = *(const float4*)(g_xl + (size_t)s5 * DD + col);               \
        }                                                                      \
        edge_compute2(sew + j * EDIM, sew + (j + 1) * EDIM,                    \
                      xa, xb, xrv, a4, wreg, acc, ds);                         \
        j += 2;                                                                \
    }

__global__ __launch_bounds__(128, 4) void k_fused(
    const int* __restrict__ ei, const float* __restrict__ ew,
    const float* __restrict__ We, const float* __restrict__ att,
    const float* __restrict__ bias, float* __restrict__ out, int n)
{
    __shared__ float sew_all[4][32 * EDIM];   // 8 KB
    __shared__ float ssum[4][DD], ssq[4][DD]; // 4 KB
    int lane = threadIdx.x & 31;
    int wid  = threadIdx.x >> 5;
    float* sew = sew_all[wid];
    int gw = blockIdx.x * 4 + wid;
    int nw = gridDim.x * 4;
    int col = lane * 4;

    ull wreg[8][4];
    #pragma unroll
    for (int dp = 0; dp < 8; dp++) {
        #pragma unroll
        for (int c = 0; c < 4; c++) {
            F2U t;
            t.f.x = __ldg(We + (2 * dp)     * DD + col + c);
            t.f.y = __ldg(We + (2 * dp + 1) * DD + col + c);
            wreg[dp][c] = t.u;
        }
    }
    float4 a4 = ((const float4*)att)[lane];
    float4 b4 = ((const float4*)bias)[lane];
    float4 sacc = make_float4(0.f, 0.f, 0.f, 0.f);
    float4 qacc = make_float4(0.f, 0.f, 0.f, 0.f);

    for (int v = gw; v < n; v += nw) {
        int start = g_off[v];
        int end   = g_off[v + 1];
        float4 xrv = *(const float4*)(g_xr + (size_t)v * DD + col);
        float4 acc = make_float4(0.f, 0.f, 0.f, 0.f);
        float ds = 0.f;

        for (int c0 = start; c0 < end; c0 += 32) {
            int m = min(32, end - c0);
            int sL = 0;
            if (lane < m) {
                int eL = g_perm[c0 + lane];
                sL = __ldg(ei + eL);
                const float4* src = (const float4*)(ew + (size_t)eL * EDIM);
                float4* dst = (float4*)(sew + lane * EDIM);
                dst[0] = src[0]; dst[1] = src[1]; dst[2] = src[2]; dst[3] = src[3];
            }
            __syncwarp();

            int s0 = __shfl_sync(FULLMASK, sL, 0);
            int s1 = __shfl_sync(FULLMASK, sL, 1);
            int s2 = __shfl_sync(FULLMASK, sL, 2);
            int s3 = __shfl_sync(FULLMASK, sL, 3);
            float4 xq0 = *(const float4*)(g_xl + (size_t)s0 * DD + col);
            float4 xq1 = *(const float4*)(g_xl + (size_t)s1 * DD + col);
            float4 xq2 = *(const float4*)(g_xl + (size_t)s2 * DD + col);
            float4 xq3 = *(const float4*)(g_xl + (size_t)s3 * DD + col);

            int j = 0;
            if (m >= 2) {
                while (true) {
                    PAIR_STAGE(xq0, xq1)        // edges j, j+1
                    if (j + 1 >= m) break;
                    PAIR_STAGE(xq2, xq3)        // edges j, j+1
                    if (j + 1 >= m) break;
                }
            }
            if (j < m) {
                // single tail edge; its xl is in xq0 (j%4==0) or xq2 (j%4==2)
                float4 xa = ((j & 2) == 0) ? xq0 : xq2;
                edge_compute(sew + j * EDIM, xa, xrv, a4, wreg, acc, ds);
            }
            __syncwarp();
        }
        float invd = (end > start) ? 1.f / ds : 0.f;
        float4 o = make_float4(fmaf(acc.x, invd, b4.x), fmaf(acc.y, invd, b4.y),
                               fmaf(acc.z, invd, b4.z), fmaf(acc.w, invd, b4.w));
        *(float4*)(out + (size_t)v * DD + col) = o;
        sacc.x += o.x; sacc.y += o.y; sacc.z += o.z; sacc.w += o.w;
        qacc.x = fmaf(o.x, o.x, qacc.x);
        qacc.y = fmaf(o.y, o.y, qacc.y);
        qacc.z = fmaf(o.z, o.z, qacc.z);
        qacc.w = fmaf(o.w, o.w, qacc.w);
    }

    *(float4*)&ssum[wid][col] = sacc;
    *(float4*)&ssq[wid][col]  = qacc;
    __syncthreads();
    int ch = threadIdx.x;
    float s = ssum[0][ch] + ssum[1][ch] + ssum[2][ch] + ssum[3][ch];
    float q = ssq[0][ch]  + ssq[1][ch]  + ssq[2][ch]  + ssq[3][ch];
    atomicAdd(&g_sum[ch], s);
    atomicAdd(&g_sumsq[ch], q);
}

// ---------------- launch 5: BN finalize + apply ----------------
__global__ __launch_bounds__(256) void k_apply(
    const float* __restrict__ gamma, const float* __restrict__ beta,
    float* __restrict__ out, int n)
{
    __shared__ float ssc[DD], ssh[DD];
    int t = threadIdx.x;
    if (t < DD) {
        float invn = 1.f / (float)n;
        float mean = g_sum[t] * invn;
        float var  = g_sumsq[t] * invn - mean * mean;
        if (var < 0.f) var = 0.f;
        float inv = rsqrtf(var + 1e-5f);
        float sc = gamma[t] * inv;
        ssc[t] = sc;
        ssh[t] = beta[t] - mean * sc;
    }
    __syncthreads();
    int i = blockIdx.x * blockDim.x + t;
    int total = n * (DD / 4);
    if (i < total) {
        float4 v = ((float4*)out)[i];
        float4 sc = ((float4*)ssc)[i & 31];
        float4 sh = ((float4*)ssh)[i & 31];
        float yx = fmaf(v.x, sc.x, sh.x);
        float yy = fmaf(v.y, sc.y, sh.y);
        float yz = fmaf(v.z, sc.z, sh.z);
        float yw = fmaf(v.w, sc.w, sh.w);
        v.x = yx > 0.f ? yx : 0.01f * yx;
        v.y = yy > 0.f ? yy : 0.01f * yy;
        v.z = yz > 0.f ? yz : 0.01f * yz;
        v.w = yw > 0.f ? yw : 0.01f * yw;
        ((float4*)out)[i] = v;
    }
}

// ---------------- launch ----------------
extern "C" void kernel_launch(void* const* d_in, const int* in_sizes, int n_in,
                              void* d_out, int out_size)
{
    const int*   x     = (const int*)  d_in[0];
    const int*   ei    = (const int*)  d_in[1];
    const float* ew    = (const float*)d_in[2];
    const float* emb   = (const float*)d_in[3];
    const float* Wl    = (const float*)d_in[4];
    const float* bl    = (const float*)d_in[5];
    const float* Wr    = (const float*)d_in[6];
    const float* br    = (const float*)d_in[7];
    const float* att   = (const float*)d_in[8];
    const float* We    = (const float*)d_in[9];
    const float* bias  = (const float*)d_in[10];
    const float* gamma = (const float*)d_in[11];
    const float* beta  = (const float*)d_in[12];
    float* out = (float*)d_out;

    int n = in_sizes[0];
    int E = in_sizes[1] / 2;
    int nb = (n + 1023) / 1024;
    int eb = (E + 255) / 256;

    k_pre<<<eb, 256>>>(Wl, Wr, ei, E);                       // 1
    k_scan<<<nb, 256>>>(n);                                  // 2
    k_nodescatter<<<296 + eb, 256>>>(x, emb, bl, br, ei, n, E, 296);  // 3
    k_fused<<<592, 128>>>(ei, ew, We, att, bias, out, n);    // 4 -> ncu capture
    k_apply<<<(n * (DD / 4) + 255) / 256, 256>>>(gamma, beta, out, n);  // 5
}